// round 1
// baseline (speedup 1.0000x reference)
#include <cuda_runtime.h>
#include <cstdint>

#define GRID_G 128
#define RMIN_F (-1.5f)
#define STEP_F (3.0f / 128.0f)

// ---------------------------------------------------------------------------
// Kernel 1: copy voxel_array -> out_voxel (vectorized float4)
// ---------------------------------------------------------------------------
__global__ void voxel_copy_kernel(const float4* __restrict__ src,
                                  float4* __restrict__ dst, int n4) {
    int i = blockIdx.x * blockDim.x + threadIdx.x;
    if (i < n4) dst[i] = src[i];
}

// ---------------------------------------------------------------------------
// Kernel 2: per-point trilinear gather + value write + scatter-add of diff
// ---------------------------------------------------------------------------
__global__ void __launch_bounds__(256)
point_kernel(const int* __restrict__ t_arr,
             const float* __restrict__ pos,
             const float* __restrict__ lr_p,
             const float* __restrict__ sigma_arr,
             const float* __restrict__ tgt,
             const float* __restrict__ voxel,
             float* __restrict__ out_value,
             float* __restrict__ out_voxel,
             int N) {
    int i = blockIdx.x * blockDim.x + threadIdx.x;
    if (i >= N) return;

    const float lr = __ldg(lr_p);

    float px = pos[3 * i + 0];
    float py = pos[3 * i + 1];
    float pz = pos[3 * i + 2];

    float sx = px - RMIN_F;
    float sy = py - RMIN_F;
    float sz = pz - RMIN_F;

    // min_idx = floor(pos_s / STEP)   (match reference: true division)
    int ix = (int)floorf(sx / STEP_F);
    int iy = (int)floorf(sy / STEP_F);
    int iz = (int)floorf(sz / STEP_F);

    // frac = mod(pos_s, STEP) / STEP
    float u = fmodf(sx, STEP_F) / STEP_F;
    float v = fmodf(sy, STEP_F) / STEP_F;
    float w = fmodf(sz, STEP_F) / STEP_F;

    // clamped vertex indices
    int x0 = min(max(ix,     0), GRID_G - 1);
    int x1 = min(max(ix + 1, 0), GRID_G - 1);
    int y0 = min(max(iy,     0), GRID_G - 1);
    int y1 = min(max(iy + 1, 0), GRID_G - 1);
    int z0 = min(max(iz,     0), GRID_G - 1);
    int z1 = min(max(iz + 1, 0), GRID_G - 1);

    float cu0 = 1.0f - u, cv0 = 1.0f - v, cw0 = 1.0f - w;

    // coefs in reference offset order:
    // (0,0,0),(1,0,0),(0,1,0),(1,1,0),(0,0,1),(1,0,1),(0,1,1),(1,1,1)
    float c[8];
    c[0] = cu0 * cv0 * cw0;
    c[1] = u   * cv0 * cw0;
    c[2] = cu0 * v   * cw0;
    c[3] = u   * v   * cw0;
    c[4] = cu0 * cv0 * w;
    c[5] = u   * cv0 * w;
    c[6] = cu0 * v   * w;
    c[7] = u   * v   * w;

    int ti = t_arr[i];
    // linear index of vertex (t, x, y, z) into (T, G, G, G, 3):
    int base_t = ti * (GRID_G * GRID_G * GRID_G);

    int vidx[8];
    {
        int bx0 = (base_t + x0 * (GRID_G * GRID_G));
        int bx1 = (base_t + x1 * (GRID_G * GRID_G));
        int b00 = (bx0 + y0 * GRID_G);
        int b10 = (bx1 + y0 * GRID_G);
        int b01 = (bx0 + y1 * GRID_G);
        int b11 = (bx1 + y1 * GRID_G);
        vidx[0] = (b00 + z0) * 3;   // (0,0,0) -> x0,y0,z0
        vidx[1] = (b10 + z0) * 3;   // (1,0,0) -> x1,y0,z0
        vidx[2] = (b01 + z0) * 3;   // (0,1,0) -> x0,y1,z0
        vidx[3] = (b11 + z0) * 3;   // (1,1,0) -> x1,y1,z0
        vidx[4] = (b00 + z1) * 3;   // (0,0,1)
        vidx[5] = (b10 + z1) * 3;   // (1,0,1)
        vidx[6] = (b01 + z1) * 3;   // (0,1,1)
        vidx[7] = (b11 + z1) * 3;   // (1,1,1)
    }

    // gather vertex values
    float vv[8][3];
#pragma unroll
    for (int k = 0; k < 8; k++) {
        vv[k][0] = __ldg(&voxel[vidx[k] + 0]);
        vv[k][1] = __ldg(&voxel[vidx[k] + 1]);
        vv[k][2] = __ldg(&voxel[vidx[k] + 2]);
    }

    // value = sum_k c[k] * vv[k]
    float val0 = 0.0f, val1 = 0.0f, val2 = 0.0f;
#pragma unroll
    for (int k = 0; k < 8; k++) {
        val0 += c[k] * vv[k][0];
        val1 += c[k] * vv[k][1];
        val2 += c[k] * vv[k][2];
    }
    out_value[3 * i + 0] = val0;
    out_value[3 * i + 1] = val1;
    out_value[3 * i + 2] = val2;

    float sw = 1.0f - expf(-sigma_arr[i]);
    float scale = lr * sw;

    float t0 = tgt[3 * i + 0];
    float t1 = tgt[3 * i + 1];
    float t2 = tgt[3 * i + 2];

#pragma unroll
    for (int k = 0; k < 8; k++) {
        // lambda = sigmoid(lr * sw * c[k])
        float x = scale * c[k];
        float lam = 1.0f / (1.0f + expf(-x));
        float d0 = lam * (t0 - vv[k][0]);
        float d1 = lam * (t1 - vv[k][1]);
        float d2 = lam * (t2 - vv[k][2]);
        atomicAdd(&out_voxel[vidx[k] + 0], d0);
        atomicAdd(&out_voxel[vidx[k] + 1], d1);
        atomicAdd(&out_voxel[vidx[k] + 2], d2);
    }
}

// ---------------------------------------------------------------------------
// Launch
// Inputs (metadata order): t, pos, lr, sigma, target_norm, voxel_array
// Output: value (N*3 f32) followed by new_voxel (T*G*G*G*3 f32)
// ---------------------------------------------------------------------------
extern "C" void kernel_launch(void* const* d_in, const int* in_sizes, int n_in,
                              void* d_out, int out_size) {
    const int*   t_arr  = (const int*)d_in[0];
    const float* pos    = (const float*)d_in[1];
    const float* lr     = (const float*)d_in[2];
    const float* sigma  = (const float*)d_in[3];
    const float* tgt    = (const float*)d_in[4];
    const float* voxel  = (const float*)d_in[5];

    const int N = in_sizes[0];                // 1048576 points
    const int voxel_elems = in_sizes[5];      // 8*128^3*3 = 50331648

    float* out_value = (float*)d_out;
    float* out_voxel = out_value + (size_t)3 * N;

    // 1) copy voxel_array into output region (float4 vectorized; size % 4 == 0)
    {
        int n4 = voxel_elems / 4;
        int threads = 256;
        int blocks = (n4 + threads - 1) / threads;
        voxel_copy_kernel<<<blocks, threads>>>((const float4*)voxel,
                                               (float4*)out_voxel, n4);
    }

    // 2) per-point compute + scatter
    {
        int threads = 256;
        int blocks = (N + threads - 1) / threads;
        point_kernel<<<blocks, threads>>>(t_arr, pos, lr, sigma, tgt, voxel,
                                          out_value, out_voxel, N);
    }
}

// round 3
// speedup vs baseline: 1.1063x; 1.1063x over previous
#include <cuda_runtime.h>
#include <cstdint>

#define GRID_G 128
#define RMIN_F (-1.5f)
#define STEP_F (3.0f / 128.0f)

// ---------------------------------------------------------------------------
// Kernel 1: copy voxel_array -> out_voxel (vectorized float4)
// ---------------------------------------------------------------------------
__global__ void voxel_copy_kernel(const float4* __restrict__ src,
                                  float4* __restrict__ dst, int n4) {
    int i = blockIdx.x * blockDim.x + threadIdx.x;
    if (i < n4) dst[i] = src[i];
}

// vector reduction helpers --------------------------------------------------
__device__ __forceinline__ void red_add_f32(float* p, float a) {
    asm volatile("red.global.add.f32 [%0], %1;" :: "l"(p), "f"(a) : "memory");
}
__device__ __forceinline__ void red_add_v2f32(float* p, float a, float b) {
    asm volatile("red.global.add.v2.f32 [%0], {%1, %2};"
                 :: "l"(p), "f"(a), "f"(b) : "memory");
}
// Add 3 floats starting at elem index `idx` (4B elems). 8B-aligned iff idx even.
__device__ __forceinline__ void red_add_vec3(float* base, int idx,
                                             float d0, float d1, float d2) {
    float* p = base + idx;
    if ((idx & 1) == 0) {
        red_add_v2f32(p, d0, d1);
        red_add_f32(p + 2, d2);
    } else {
        red_add_f32(p, d0);
        red_add_v2f32(p + 1, d1, d2);
    }
}

// ---------------------------------------------------------------------------
// Kernel 2: per-point trilinear gather + value write + scatter-add of diff
// ---------------------------------------------------------------------------
__global__ void __launch_bounds__(256, 5)
point_kernel(const int* __restrict__ t_arr,
             const float* __restrict__ pos,
             const float* __restrict__ lr_p,
             const float* __restrict__ sigma_arr,
             const float* __restrict__ tgt,
             const float* __restrict__ voxel,
             float* __restrict__ out_value,
             float* __restrict__ out_voxel,
             int N) {
    int i = blockIdx.x * blockDim.x + threadIdx.x;
    if (i >= N) return;

    const float lr = __ldg(lr_p);

    float sx = pos[3 * i + 0] - RMIN_F;
    float sy = pos[3 * i + 1] - RMIN_F;
    float sz = pos[3 * i + 2] - RMIN_F;

    int ix = (int)floorf(sx / STEP_F);
    int iy = (int)floorf(sy / STEP_F);
    int iz = (int)floorf(sz / STEP_F);

    float u = fmodf(sx, STEP_F) / STEP_F;
    float v = fmodf(sy, STEP_F) / STEP_F;
    float w = fmodf(sz, STEP_F) / STEP_F;

    int x0 = min(max(ix,     0), GRID_G - 1);
    int x1 = min(max(ix + 1, 0), GRID_G - 1);
    int y0 = min(max(iy,     0), GRID_G - 1);
    int y1 = min(max(iy + 1, 0), GRID_G - 1);
    int z0 = min(max(iz,     0), GRID_G - 1);
    int z1 = min(max(iz + 1, 0), GRID_G - 1);

    float cu0 = 1.0f - u, cv0 = 1.0f - v, cw0 = 1.0f - w;

    // coefs in reference offset order:
    // (0,0,0),(1,0,0),(0,1,0),(1,1,0),(0,0,1),(1,0,1),(0,1,1),(1,1,1)
    float c[8];
    c[0] = cu0 * cv0 * cw0;
    c[1] = u   * cv0 * cw0;
    c[2] = cu0 * v   * cw0;
    c[3] = u   * v   * cw0;
    c[4] = cu0 * cv0 * w;
    c[5] = u   * cv0 * w;
    c[6] = cu0 * v   * w;
    c[7] = u   * v   * w;

    int ti = t_arr[i];
    int base_t = ti * (GRID_G * GRID_G * GRID_G);

    int vidx[8];
    {
        int bx0 = base_t + x0 * (GRID_G * GRID_G);
        int bx1 = base_t + x1 * (GRID_G * GRID_G);
        int b00 = bx0 + y0 * GRID_G;
        int b10 = bx1 + y0 * GRID_G;
        int b01 = bx0 + y1 * GRID_G;
        int b11 = bx1 + y1 * GRID_G;
        vidx[0] = (b00 + z0) * 3;
        vidx[1] = (b10 + z0) * 3;
        vidx[2] = (b01 + z0) * 3;
        vidx[3] = (b11 + z0) * 3;
        vidx[4] = (b00 + z1) * 3;
        vidx[5] = (b10 + z1) * 3;
        vidx[6] = (b01 + z1) * 3;
        vidx[7] = (b11 + z1) * 3;
    }

    // gather vertex values (batched for MLP)
    float vv[8][3];
#pragma unroll
    for (int k = 0; k < 8; k++) {
        vv[k][0] = __ldg(&voxel[vidx[k] + 0]);
        vv[k][1] = __ldg(&voxel[vidx[k] + 1]);
        vv[k][2] = __ldg(&voxel[vidx[k] + 2]);
    }

    // value = sum_k c[k] * vv[k]
    float val0 = 0.0f, val1 = 0.0f, val2 = 0.0f;
#pragma unroll
    for (int k = 0; k < 8; k++) {
        val0 += c[k] * vv[k][0];
        val1 += c[k] * vv[k][1];
        val2 += c[k] * vv[k][2];
    }
    out_value[3 * i + 0] = val0;
    out_value[3 * i + 1] = val1;
    out_value[3 * i + 2] = val2;

    float sw = 1.0f - __expf(-sigma_arr[i]);
    float scale = lr * sw;

    float t0 = tgt[3 * i + 0];
    float t1 = tgt[3 * i + 1];
    float t2 = tgt[3 * i + 2];

#pragma unroll
    for (int k = 0; k < 8; k++) {
        float x = scale * c[k];
        float lam = __fdividef(1.0f, 1.0f + __expf(-x));
        float d0 = lam * (t0 - vv[k][0]);
        float d1 = lam * (t1 - vv[k][1]);
        float d2 = lam * (t2 - vv[k][2]);
        red_add_vec3(out_voxel, vidx[k], d0, d1, d2);
    }
}

// ---------------------------------------------------------------------------
// Launch
// Inputs (metadata order): t, pos, lr, sigma, target_norm, voxel_array
// Output: value (N*3 f32) followed by new_voxel (T*G*G*G*3 f32)
// ---------------------------------------------------------------------------
extern "C" void kernel_launch(void* const* d_in, const int* in_sizes, int n_in,
                              void* d_out, int out_size) {
    const int*   t_arr  = (const int*)d_in[0];
    const float* pos    = (const float*)d_in[1];
    const float* lr     = (const float*)d_in[2];
    const float* sigma  = (const float*)d_in[3];
    const float* tgt    = (const float*)d_in[4];
    const float* voxel  = (const float*)d_in[5];

    const int N = in_sizes[0];                // 1048576 points
    const int voxel_elems = in_sizes[5];      // 8*128^3*3 = 50331648

    float* out_value = (float*)d_out;
    float* out_voxel = out_value + (size_t)3 * N;

    // 1) copy voxel_array into output region
    {
        int n4 = voxel_elems / 4;
        int threads = 256;
        int blocks = (n4 + threads - 1) / threads;
        voxel_copy_kernel<<<blocks, threads>>>((const float4*)voxel,
                                               (float4*)out_voxel, n4);
    }

    // 2) per-point compute + scatter
    {
        int threads = 256;
        int blocks = (N + threads - 1) / threads;
        point_kernel<<<blocks, threads>>>(t_arr, pos, lr, sigma, tgt, voxel,
                                          out_value, out_voxel, N);
    }
}

// round 4
// speedup vs baseline: 1.1920x; 1.0774x over previous
#include <cuda_runtime.h>
#include <cstdint>

#define GRID_G 128
#define RMIN_F (-1.5f)
#define STEP_F (3.0f / 128.0f)
#define VOXEL_TOTAL (8 * GRID_G * GRID_G * GRID_G * 3)   // 50331648

// ---------------------------------------------------------------------------
// Kernel 1: copy voxel_array -> out_voxel (vectorized float4)
// ---------------------------------------------------------------------------
__global__ void voxel_copy_kernel(const float4* __restrict__ src,
                                  float4* __restrict__ dst, int n4) {
    int i = blockIdx.x * blockDim.x + threadIdx.x;
    if (i < n4) dst[i] = src[i];
}

// reduction helpers ---------------------------------------------------------
__device__ __forceinline__ void red_add_f32(float* p, float a) {
    asm volatile("red.global.add.f32 [%0], %1;" :: "l"(p), "f"(a) : "memory");
}
__device__ __forceinline__ void red_add_v2f32(float* p, float a, float b) {
    asm volatile("red.global.add.v2.f32 [%0], {%1, %2};"
                 :: "l"(p), "f"(a), "f"(b) : "memory");
}

// ---------------------------------------------------------------------------
// Process one (x,y) row-pair: vertices (z=zb) and (z=zb+1), 6 contiguous
// floats at elem index e=(b+zb)*3. Uniform 8-float window at ew=e&~1.
//   o0: 0 normally; 1 when z0==127 (both logical vertices map to zb+1).
//   ck0: coef for the z-offset-0 vertex, ck1: z-offset-1 vertex.
// ---------------------------------------------------------------------------
__device__ __forceinline__ void process_pair(
    const float* __restrict__ voxel, float* __restrict__ out_voxel,
    int b, int zb, int o0, float ck0, float ck1,
    float scale, float t0, float t1, float t2,
    float& val0, float& val1, float& val2)
{
    int e  = (b + zb) * 3;
    int ew = e & ~1;
    int q  = e & 1;
    bool fast = (ew + 8 <= VOXEL_TOTAL);

    float v0x, v0y, v0z, v1x, v1y, v1z;
    float2 wa, wb, wc, wd;
    if (fast) {
        const float2* wp = (const float2*)(voxel + ew);
        wa = __ldg(wp + 0); wb = __ldg(wp + 1);
        wc = __ldg(wp + 2); wd = __ldg(wp + 3);
        // window floats: wa.x wa.y wb.x wb.y wc.x wc.y wd.x wd.y = win[0..7]
        v1x = q ? wc.x : wb.y;            // win[q+3]
        v1y = q ? wc.y : wc.x;            // win[q+4]
        v1z = q ? wd.x : wc.y;            // win[q+5]
        float b0 = q ? wa.y : wa.x;       // win[q+0]
        float b1 = q ? wb.x : wa.y;       // win[q+1]
        float b2 = q ? wb.y : wb.x;       // win[q+2]
        v0x = o0 ? v1x : b0;
        v0y = o0 ? v1y : b1;
        v0z = o0 ? v1z : b2;
    } else {
        int e0 = e + 3 * o0;
        v0x = __ldg(voxel + e0 + 0);
        v0y = __ldg(voxel + e0 + 1);
        v0z = __ldg(voxel + e0 + 2);
        v1x = __ldg(voxel + e + 3);
        v1y = __ldg(voxel + e + 4);
        v1z = __ldg(voxel + e + 5);
    }

    val0 += ck0 * v0x + ck1 * v1x;
    val1 += ck0 * v0y + ck1 * v1y;
    val2 += ck0 * v0z + ck1 * v1z;

    float lam0 = __fdividef(1.0f, 1.0f + __expf(-scale * ck0));
    float lam1 = __fdividef(1.0f, 1.0f + __expf(-scale * ck1));

    float d00 = lam0 * (t0 - v0x), d01 = lam0 * (t1 - v0y), d02 = lam0 * (t2 - v0z);
    float d10 = lam1 * (t0 - v1x), d11 = lam1 * (t1 - v1y), d12 = lam1 * (t2 - v1z);

    // e0c -> slot q+c (z-offset-0 vertex block), e1c -> slot q+3+c
    float e00 = o0 ? 0.0f : d00;
    float e01 = o0 ? 0.0f : d01;
    float e02 = o0 ? 0.0f : d02;
    float e10 = o0 ? (d00 + d10) : d10;
    float e11 = o0 ? (d01 + d11) : d11;
    float e12 = o0 ? (d02 + d12) : d12;

    if (fast) {
        float dl0 = q ? 0.0f : e00;
        float dl1 = q ? e00  : e01;
        float dl2 = q ? e01  : e02;
        float dl3 = q ? e02  : e10;
        float dl4 = q ? e10  : e11;
        float dl5 = q ? e11  : e12;
        float dl6 = q ? e12  : 0.0f;
        float* op = out_voxel + ew;
        red_add_v2f32(op + 0, dl0, dl1);
        red_add_v2f32(op + 2, dl2, dl3);
        red_add_v2f32(op + 4, dl4, dl5);
        if (q) red_add_v2f32(op + 6, dl6, 0.0f);
    } else {
        float* op = out_voxel + e;
        red_add_f32(op + 0, e00);
        red_add_f32(op + 1, e01);
        red_add_f32(op + 2, e02);
        red_add_f32(op + 3, e10);
        red_add_f32(op + 4, e11);
        red_add_f32(op + 5, e12);
    }
}

// ---------------------------------------------------------------------------
// Kernel 2: per-point trilinear gather + value write + scatter-add of diff
// ---------------------------------------------------------------------------
__global__ void __launch_bounds__(256, 5)
point_kernel(const int* __restrict__ t_arr,
             const float* __restrict__ pos,
             const float* __restrict__ lr_p,
             const float* __restrict__ sigma_arr,
             const float* __restrict__ tgt,
             const float* __restrict__ voxel,
             float* __restrict__ out_value,
             float* __restrict__ out_voxel,
             int N) {
    int i = blockIdx.x * blockDim.x + threadIdx.x;
    if (i >= N) return;

    const float lr = __ldg(lr_p);

    // ---- uniform windowed input loads (pos, tgt): 2x LDG.64 each ----
    float px, py, pz, t0, t1, t2;
    int p0 = 3 * i;
    if (i < N - 1) {
        int pw = p0 & ~1;
        int qp = p0 & 1;
        float2 pa = __ldg((const float2*)(pos + pw));
        float2 pb = __ldg((const float2*)(pos + pw + 2));
        px = qp ? pa.y : pa.x;
        py = qp ? pb.x : pa.y;
        pz = qp ? pb.y : pb.x;
        float2 ga = __ldg((const float2*)(tgt + pw));
        float2 gb = __ldg((const float2*)(tgt + pw + 2));
        t0 = qp ? ga.y : ga.x;
        t1 = qp ? gb.x : ga.y;
        t2 = qp ? gb.y : gb.x;
    } else {
        px = __ldg(pos + p0 + 0); py = __ldg(pos + p0 + 1); pz = __ldg(pos + p0 + 2);
        t0 = __ldg(tgt + p0 + 0); t1 = __ldg(tgt + p0 + 1); t2 = __ldg(tgt + p0 + 2);
    }

    float sx = px - RMIN_F;
    float sy = py - RMIN_F;
    float sz = pz - RMIN_F;

    int ix = (int)floorf(sx / STEP_F);
    int iy = (int)floorf(sy / STEP_F);
    int iz = (int)floorf(sz / STEP_F);

    float u = fmodf(sx, STEP_F) / STEP_F;
    float v = fmodf(sy, STEP_F) / STEP_F;
    float w = fmodf(sz, STEP_F) / STEP_F;

    int x0 = min(max(ix,     0), GRID_G - 1);
    int x1 = min(max(ix + 1, 0), GRID_G - 1);
    int y0 = min(max(iy,     0), GRID_G - 1);
    int y1 = min(max(iy + 1, 0), GRID_G - 1);
    int z0 = min(max(iz,     0), GRID_G - 1);

    int zb = min(z0, GRID_G - 2);
    int o0 = z0 - zb;                 // 0 normally, 1 at z-top boundary

    float cu0 = 1.0f - u, cv0 = 1.0f - v, cw0 = 1.0f - w;

    // coefs, reference offset order:
    // k: (0,0,0),(1,0,0),(0,1,0),(1,1,0),(0,0,1),(1,0,1),(0,1,1),(1,1,1)
    float c0 = cu0 * cv0 * cw0;
    float c1 = u   * cv0 * cw0;
    float c2 = cu0 * v   * cw0;
    float c3 = u   * v   * cw0;
    float c4 = cu0 * cv0 * w;
    float c5 = u   * cv0 * w;
    float c6 = cu0 * v   * w;
    float c7 = u   * v   * w;

    int base_t = t_arr[i] * (GRID_G * GRID_G * GRID_G);
    int bx0 = base_t + x0 * (GRID_G * GRID_G);
    int bx1 = base_t + x1 * (GRID_G * GRID_G);
    int b00 = bx0 + y0 * GRID_G;      // (x0, y0)
    int b10 = bx1 + y0 * GRID_G;      // (x1, y0)
    int b01 = bx0 + y1 * GRID_G;      // (x0, y1)
    int b11 = bx1 + y1 * GRID_G;      // (x1, y1)

    float sw = 1.0f - __expf(-sigma_arr[i]);
    float scale = lr * sw;

    float val0 = 0.0f, val1 = 0.0f, val2 = 0.0f;

    process_pair(voxel, out_voxel, b00, zb, o0, c0, c4, scale, t0, t1, t2, val0, val1, val2);
    process_pair(voxel, out_voxel, b10, zb, o0, c1, c5, scale, t0, t1, t2, val0, val1, val2);
    process_pair(voxel, out_voxel, b01, zb, o0, c2, c6, scale, t0, t1, t2, val0, val1, val2);
    process_pair(voxel, out_voxel, b11, zb, o0, c3, c7, scale, t0, t1, t2, val0, val1, val2);

    out_value[p0 + 0] = val0;
    out_value[p0 + 1] = val1;
    out_value[p0 + 2] = val2;
}

// ---------------------------------------------------------------------------
// Launch
// Inputs (metadata order): t, pos, lr, sigma, target_norm, voxel_array
// Output: value (N*3 f32) followed by new_voxel (T*G*G*G*3 f32)
// ---------------------------------------------------------------------------
extern "C" void kernel_launch(void* const* d_in, const int* in_sizes, int n_in,
                              void* d_out, int out_size) {
    const int*   t_arr  = (const int*)d_in[0];
    const float* pos    = (const float*)d_in[1];
    const float* lr     = (const float*)d_in[2];
    const float* sigma  = (const float*)d_in[3];
    const float* tgt    = (const float*)d_in[4];
    const float* voxel  = (const float*)d_in[5];

    const int N = in_sizes[0];                // 1048576 points
    const int voxel_elems = in_sizes[5];      // 50331648

    float* out_value = (float*)d_out;
    float* out_voxel = out_value + (size_t)3 * N;

    // 1) copy voxel_array into output region
    {
        int n4 = voxel_elems / 4;
        int threads = 256;
        int blocks = (n4 + threads - 1) / threads;
        voxel_copy_kernel<<<blocks, threads>>>((const float4*)voxel,
                                               (float4*)out_voxel, n4);
    }

    // 2) per-point compute + scatter
    {
        int threads = 256;
        int blocks = (N + threads - 1) / threads;
        point_kernel<<<blocks, threads>>>(t_arr, pos, lr, sigma, tgt, voxel,
                                          out_value, out_voxel, N);
    }
}